// round 15
// baseline (speedup 1.0000x reference)
#include <cuda_runtime.h>
#include <math.h>

// ---------------- problem constants ----------------
#define BB   4
#define NMM  196
#define NA   64
#define NV   196
#define DIMI 768
#define NH   12
#define HD   64
#define DIMO 768
#define NKV  (NV*NA)      // 12544
#define SCALE 0.125f      // (768/12)^-0.5

#define OUT_ELEMS  (BB*NMM*DIMO)           // 602112
#define ATTN_ELEMS ((size_t)BB*NH*NMM*NKV) // 118013952
#define NROWS      (BB*NH*NMM)             // 9408 attn rows

typedef unsigned long long ull;

// ---------------- scratch (no allocs allowed) ----------------
// input projections: split-K x4 partials, consumer sums on load
__device__ float g_q0  [BB*NMM*DIMO];
__device__ float g_q1  [BB*NMM*DIMO];
__device__ float g_q2  [BB*NMM*DIMO];
__device__ float g_q3  [BB*NMM*DIMO];
__device__ float g_kvv0[BB*NV*2*DIMO];
__device__ float g_kvv1[BB*NV*2*DIMO];
__device__ float g_kvv2[BB*NV*2*DIMO];
__device__ float g_kvv3[BB*NV*2*DIMO];
__device__ float g_kva0[BB*NA*2*DIMO];
__device__ float g_kva1[BB*NA*2*DIMO];
__device__ float g_kva2[BB*NA*2*DIMO];
__device__ float g_kva3[BB*NA*2*DIMO];
__device__ float g_pv  [BB*NH*NMM*NV];
__device__ float g_pa  [BB*NH*NMM*NA];
__device__ float g_oav [BB*NMM*DIMO];
// output projection: split-K x8 partials
__device__ float g_op[8][OUT_ELEMS];

// ---------------- f32x2 helpers ----------------
__device__ __forceinline__ ull pack2(float x, float y) {
    ull r; asm("mov.b64 %0, {%1,%2};" : "=l"(r) : "f"(x), "f"(y)); return r;
}
__device__ __forceinline__ float2 unpk2(ull v) {
    float2 r; asm("mov.b64 {%0,%1}, %2;" : "=f"(r.x), "=f"(r.y) : "l"(v)); return r;
}
__device__ __forceinline__ ull fma2(ull a, ull b, ull c) {
    ull d; asm("fma.rn.f32x2 %0, %1, %2, %3;" : "=l"(d) : "l"(a), "l"(b), "l"(c)); return d;
}

// ---------------- warp reductions ----------------
__device__ __forceinline__ float warpMax(float v) {
#pragma unroll
    for (int o = 16; o; o >>= 1) v = fmaxf(v, __shfl_xor_sync(0xffffffffu, v, o));
    return v;
}
__device__ __forceinline__ float warpSum(float v) {
#pragma unroll
    for (int o = 16; o; o >>= 1) v += __shfl_xor_sync(0xffffffffu, v, o);
    return v;
}

// sum-of-4-partials loaders
__device__ __forceinline__ float2 sum4_f2(const float* p0, const float* p1,
                                          const float* p2, const float* p3, size_t off) {
    float2 a = *(const float2*)(p0 + off);
    float2 b = *(const float2*)(p1 + off);
    float2 c = *(const float2*)(p2 + off);
    float2 d = *(const float2*)(p3 + off);
    return make_float2(a.x + b.x + c.x + d.x, a.y + b.y + c.y + d.y);
}

// ================= 128x128 FFMA2 GEMM tile, split-K =================
#define GP 132
#define GEMM_SMEM (2 * 16 * GP)   // floats

template<int M, int N, int K>
__device__ __forceinline__ void gemm128(const float* __restrict__ A,
                                        const float* __restrict__ B,
                                        float* __restrict__ C,
                                        int mt, int nt, int kbeg, int kend,
                                        float* sm)
{
    float* As = sm;            // [16][GP] k-major
    float* Bs = sm + 16 * GP;  // [16][GP]
    const int tid = threadIdx.x;
    const int tx = tid & 15, ty = tid >> 4;
    const int m0 = mt * 128, n0 = nt * 128;

    const int ar = tid >> 1, ak = (tid & 1) * 8;
    const int br = tid >> 4, bc = (tid & 15) * 8;

    ull acc[8][4];
#pragma unroll
    for (int i = 0; i < 8; i++)
#pragma unroll
        for (int j = 0; j < 4; j++) acc[i][j] = 0ULL;

    const bool aval = (m0 + ar < M);
    const float* Aptr = A + (size_t)(m0 + ar) * K + kbeg + ak;
    const float* Bptr = B + (size_t)(kbeg + br) * N + n0 + bc;

    const float4 z4 = make_float4(0.f, 0.f, 0.f, 0.f);
    float4 ra0 = aval ? *(const float4*)(Aptr)     : z4;
    float4 ra1 = aval ? *(const float4*)(Aptr + 4) : z4;
    float4 rb0 = *(const float4*)(Bptr);
    float4 rb1 = *(const float4*)(Bptr + 4);

    for (int k0 = kbeg; k0 < kend; k0 += 16) {
        As[(ak + 0) * GP + ar] = ra0.x;
        As[(ak + 1) * GP + ar] = ra0.y;
        As[(ak + 2) * GP + ar] = ra0.z;
        As[(ak + 3) * GP + ar] = ra0.w;
        As[(ak + 4) * GP + ar] = ra1.x;
        As[(ak + 5) * GP + ar] = ra1.y;
        As[(ak + 6) * GP + ar] = ra1.z;
        As[(ak + 7) * GP + ar] = ra1.w;
        *(float4*)&Bs[br * GP + bc]     = rb0;
        *(float4*)&Bs[br * GP + bc + 4] = rb1;
        __syncthreads();

        if (k0 + 16 < kend) {
            Aptr += 16;
            Bptr += (size_t)16 * N;
            ra0 = aval ? *(const float4*)(Aptr)     : z4;
            ra1 = aval ? *(const float4*)(Aptr + 4) : z4;
            rb0 = *(const float4*)(Bptr);
            rb1 = *(const float4*)(Bptr + 4);
        }

#pragma unroll
        for (int k = 0; k < 16; k++) {
            float4 av0 = *(const float4*)&As[k * GP + ty * 8];
            float4 av1 = *(const float4*)&As[k * GP + ty * 8 + 4];
            ulonglong2 bu0 = *(const ulonglong2*)&Bs[k * GP + tx * 8];
            ulonglong2 bu1 = *(const ulonglong2*)&Bs[k * GP + tx * 8 + 4];
            ull bv0 = bu0.x, bv1 = bu0.y, bv2 = bu1.x, bv3 = bu1.y;
            float a[8] = {av0.x, av0.y, av0.z, av0.w, av1.x, av1.y, av1.z, av1.w};
#pragma unroll
            for (int i = 0; i < 8; i++) {
                ull d = pack2(a[i], a[i]);
                acc[i][0] = fma2(d, bv0, acc[i][0]);
                acc[i][1] = fma2(d, bv1, acc[i][1]);
                acc[i][2] = fma2(d, bv2, acc[i][2]);
                acc[i][3] = fma2(d, bv3, acc[i][3]);
            }
        }
        __syncthreads();
    }

#pragma unroll
    for (int i = 0; i < 8; i++) {
        int gm = m0 + ty * 8 + i;
        if (gm >= M) continue;
        float2 p0 = unpk2(acc[i][0]), p1 = unpk2(acc[i][1]);
        float2 p2 = unpk2(acc[i][2]), p3 = unpk2(acc[i][3]);
        float* crow = &C[(size_t)gm * N + n0 + tx * 8];
        *(float4*)(crow)     = make_float4(p0.x, p0.y, p1.x, p1.y);
        *(float4*)(crow + 4) = make_float4(p2.x, p2.y, p3.x, p3.y);
    }
}

// input projections, split-K x4 -> 600 blocks (12 slabs each)
__global__ __launch_bounds__(256, 2)
void gemm3_kernel(const float* __restrict__ xmm, const float* __restrict__ Wq,
                  const float* __restrict__ xv,  const float* __restrict__ xa,
                  const float* __restrict__ Wkv)
{
    __shared__ __align__(16) float sm[GEMM_SMEM];
    int bid = blockIdx.x;
    if (bid < 168) {                       // q: 42 tiles x 4
        int t = bid >> 2, c = bid & 3;
        float* dst = (c == 0) ? g_q0 : (c == 1) ? g_q1 : (c == 2) ? g_q2 : g_q3;
        gemm128<784, 768, 768>(xmm, Wq, dst, t / 6, t % 6, c * 192, c * 192 + 192, sm);
    } else if (bid < 504) {                // kvv: 84 tiles x 4
        int l = bid - 168; int t = l >> 2, c = l & 3;
        float* dst = (c == 0) ? g_kvv0 : (c == 1) ? g_kvv1 : (c == 2) ? g_kvv2 : g_kvv3;
        gemm128<784, 1536, 768>(xv, Wkv, dst, t / 12, t % 12, c * 192, c * 192 + 192, sm);
    } else {                               // kva: 24 tiles x 4
        int l = bid - 504; int t = l >> 2, c = l & 3;
        float* dst = (c == 0) ? g_kva0 : (c == 1) ? g_kva1 : (c == 2) ? g_kva2 : g_kva3;
        gemm128<256, 1536, 768>(xa, Wkv + (size_t)DIMI * 1536, dst,
                                t / 12, t % 12, c * 192, c * 192 + 192, sm);
    }
}

// output projection split-K x8 -> 336 blocks (6 slabs each)
__global__ __launch_bounds__(256, 2)
void proj_kernel(const float* __restrict__ Wproj)
{
    __shared__ __align__(16) float sm[GEMM_SMEM];
    int t = blockIdx.x >> 3, c = blockIdx.x & 7;
    gemm128<784, 768, 768>(g_oav, Wproj, g_op[c], t / 6, t % 6, c * 96, c * 96 + 96, sm);
}

// epilogue: out = sum_{c=0..7} op[c] + bias
__global__ __launch_bounds__(256)
void proj_epilogue_kernel(const float* __restrict__ bproj, float* __restrict__ out)
{
    int i4 = blockIdx.x * 256 + threadIdx.x;
    if (i4 >= OUT_ELEMS / 4) return;
    float4 r = ((const float4*)g_op[0])[i4];
#pragma unroll
    for (int c = 1; c < 8; c++) {
        float4 p = ((const float4*)g_op[c])[i4];
        r.x += p.x; r.y += p.y; r.z += p.z; r.w += p.w;
    }
    int nb = (i4 * 4) % DIMO;
    r.x += bproj[nb + 0]; r.y += bproj[nb + 1];
    r.z += bproj[nb + 2]; r.w += bproj[nb + 3];
    ((float4*)out)[i4] = r;
}

// ============ scores + softmax (warp-per-q), K tiles only ============
#define QC 28
#define KPAD 66
#define SC_SMEM  ((NV * KPAD + NA * KPAD + 8 * KPAD) * 4)

__global__ __launch_bounds__(256, 2)
void scores_kernel() {
    extern __shared__ float smem[];
    float* Kv  = smem;                 // 196*66
    float* Ka  = Kv + NV * KPAD;       // 64*66
    float* qsm = Ka + NA * KPAD;       // 8*66

    const int blk = blockIdx.x;
    const int c = blk % 7;
    const int h = (blk / 7) % NH;
    const int b = blk / (7 * NH);
    const int tid = threadIdx.x, lane = tid & 31, w = tid >> 5;

    for (int idx = tid; idx < 260 * 32; idx += 256) {
        int r = idx >> 5, d2 = (idx & 31) * 2;
        if (r < NV) {
            size_t off = (size_t)(b * NV + r) * 1536 + h * HD + d2;
            *(float2*)&Kv[r * KPAD + d2] = sum4_f2(g_kvv0, g_kvv1, g_kvv2, g_kvv3, off);
        } else {
            int j = r - NV;
            size_t off = (size_t)(b * NA + j) * 1536 + h * HD + d2;
            *(float2*)&Ka[j * KPAD + d2] = sum4_f2(g_kva0, g_kva1, g_kva2, g_kva3, off);
        }
    }
    __syncthreads();

#pragma unroll 1
    for (int t0 = 0; t0 < 4; t0++) {
        int rloc = t0 * 8 + w;
        if (rloc >= QC) break;
        int qq = c * QC + rloc;

        size_t qoff = (size_t)(b * NMM + qq) * DIMO + h * HD + lane * 2;
        *(float2*)&qsm[w * KPAD + lane * 2] = sum4_f2(g_q0, g_q1, g_q2, g_q3, qoff);
        __syncwarp();
        ull q2[32];
#pragma unroll
        for (int u = 0; u < 32; u++) q2[u] = *(const ull*)&qsm[w * KPAD + 2 * u];

        float sv[7], sa[2];
#pragma unroll
        for (int t = 0; t < 7; t++) {
            int i = 32 * t + lane;
            float s = -1e30f;
            if (i < NV) {
                const float* kr = &Kv[i * KPAD];
                ull acc = 0ULL;
#pragma unroll
                for (int u = 0; u < 32; u++) acc = fma2(q2[u], *(const ull*)&kr[2 * u], acc);
                float2 p = unpk2(acc);
                s = (p.x + p.y) * SCALE;
            }
            sv[t] = s;
        }
#pragma unroll
        for (int t = 0; t < 2; t++) {
            int j = 32 * t + lane;
            const float* kr = &Ka[j * KPAD];
            ull acc = 0ULL;
#pragma unroll
            for (int u = 0; u < 32; u++) acc = fma2(q2[u], *(const ull*)&kr[2 * u], acc);
            float2 p = unpk2(acc);
            sa[t] = (p.x + p.y) * SCALE;
        }

        float mv = sv[0];
#pragma unroll
        for (int t = 1; t < 7; t++) mv = fmaxf(mv, sv[t]);
        mv = warpMax(mv);
        float ma = fmaxf(sa[0], sa[1]);
        ma = warpMax(ma);

        float ev[7], ea[2], Sv = 0.f, Sa = 0.f;
#pragma unroll
        for (int t = 0; t < 7; t++) { ev[t] = __expf(sv[t] - mv); Sv += ev[t]; }
#pragma unroll
        for (int t = 0; t < 2; t++) { ea[t] = __expf(sa[t] - ma); Sa += ea[t]; }
        float iEv = 1.f / warpSum(Sv);
        float iEa = 1.f / warpSum(Sa);

        size_t rowg = (size_t)(b * NH + h) * NMM + qq;
#pragma unroll
        for (int t = 0; t < 7; t++) {
            int i = 32 * t + lane;
            if (i < NV) g_pv[rowg * NV + i] = ev[t] * iEv;
        }
#pragma unroll
        for (int t = 0; t < 2; t++) g_pa[rowg * NA + 32 * t + lane] = ea[t] * iEa;
    }
}

// ============ AV kernel: 4 q-rows per warp in parallel, 3 CTAs/SM ============
#define AVB  (BB*NH*7)   // 336
#define AV_SMEM  ((NV * KPAD + NA * KPAD) * 4)

__global__ __launch_bounds__(256, 3)
void av_kernel()
{
    extern __shared__ float smem[];
    float* Vv = smem;              // 196*66
    float* Va = Vv + NV * KPAD;    // 64*66
    const int bid = blockIdx.x;
    const int c = bid % 7;
    const int h = (bid / 7) % NH;
    const int b = bid / (7 * NH);
    const int tid = threadIdx.x, lane = tid & 31, w = tid >> 5;

    for (int idx = tid; idx < 260 * 32; idx += 256) {
        int r = idx >> 5, d2 = (idx & 31) * 2;
        if (r < NV) {
            size_t off = (size_t)(b * NV + r) * 1536 + 768 + h * HD + d2;
            *(float2*)&Vv[r * KPAD + d2] = sum4_f2(g_kvv0, g_kvv1, g_kvv2, g_kvv3, off);
        } else {
            int j = r - NV;
            size_t off = (size_t)(b * NA + j) * 1536 + 768 + h * HD + d2;
            *(float2*)&Va[j * KPAD + d2] = sum4_f2(g_kva0, g_kva1, g_kva2, g_kva3, off);
        }
    }
    __syncthreads();

    // 4 rows per warp: rloc = r*8 + w
    bool valid[4];
    float ev[4][7], ea[4][2];
    int qqr[4];
#pragma unroll
    for (int r = 0; r < 4; r++) {
        int rloc = r * 8 + w;
        valid[r] = (rloc < QC);
        int qq = c * QC + (valid[r] ? rloc : 0);
        qqr[r] = qq;
        size_t rowg = (size_t)(b * NH + h) * NMM + qq;
#pragma unroll
        for (int t = 0; t < 7; t++) {
            int i = 32 * t + lane;
            ev[r][t] = (valid[r] && i < NV) ? g_pv[rowg * NV + i] : 0.f;
        }
#pragma unroll
        for (int t = 0; t < 2; t++)
            ea[r][t] = valid[r] ? g_pa[rowg * NA + 32 * t + lane] : 0.f;
    }

    ull acc[4] = {0ULL, 0ULL, 0ULL, 0ULL};

#pragma unroll
    for (int t = 0; t < 7; t++) {
        int smax = (t == 6) ? 4 : 32;
#pragma unroll
        for (int s = 0; s < 32; s++) {
            if (s >= smax) break;
            int i = 32 * t + s;
            ull vv = *(const ull*)&Vv[i * KPAD + 2 * lane];
#pragma unroll
            for (int r = 0; r < 4; r++) {
                float p = __shfl_sync(0xffffffffu, ev[r][t], s);
                acc[r] = fma2(pack2(p, p), vv, acc[r]);
            }
        }
    }
#pragma unroll
    for (int t = 0; t < 2; t++) {
#pragma unroll
        for (int s = 0; s < 32; s++) {
            int j = 32 * t + s;
            ull vv = *(const ull*)&Va[j * KPAD + 2 * lane];
#pragma unroll
            for (int r = 0; r < 4; r++) {
                float p = __shfl_sync(0xffffffffu, ea[r][t], s);
                acc[r] = fma2(pack2(p, p), vv, acc[r]);
            }
        }
    }

#pragma unroll
    for (int r = 0; r < 4; r++) {
        if (!valid[r]) continue;
        float2 o = unpk2(acc[r]);
        *(float2*)&g_oav[(size_t)(b * NMM + qqr[r]) * DIMO + h * HD + 2 * lane] = o;
    }
}

// ---------- attn materialization: lightweight 32-reg writer (R5-proven) ----------
__global__ void attn_write_kernel(float* __restrict__ attn_out) {
    __shared__ float pvs[NV];
    __shared__ __align__(16) float4 pas4[NA / 4];
    size_t row = blockIdx.x;
    int tid = threadIdx.x;

    for (int i = tid; i < NV; i += 256) pvs[i] = g_pv[row * NV + i];
    if (tid < NA / 4) pas4[tid] = ((const float4*)(g_pa + row * NA))[tid];
    __syncthreads();

    float4* out4 = (float4*)(attn_out + row * (size_t)NKV);
#pragma unroll 4
    for (int k4 = tid; k4 < NKV / 4; k4 += 256) {
        int i  = k4 >> 4;
        int j4 = k4 & 15;
        float p = pvs[i];
        float4 a = pas4[j4];
        float4 v = make_float4(p * a.x, p * a.y, p * a.z, p * a.w);
        __stcs(&out4[k4], v);
    }
}

// ---------------- host launcher ----------------
extern "C" void kernel_launch(void* const* d_in, const int* in_sizes, int n_in,
                              void* d_out, int out_size)
{
    const float* xmm   = (const float*)d_in[0];
    const float* xa    = (const float*)d_in[1];
    const float* xv    = (const float*)d_in[2];
    const float* Wq    = (const float*)d_in[3];
    const float* Wkv   = (const float*)d_in[4];
    const float* Wproj = (const float*)d_in[5];
    const float* bproj = (const float*)d_in[6];
    float* out = (float*)d_out;

    static cudaStream_t s1 = nullptr;
    static cudaEvent_t evFork = nullptr, evJoin = nullptr;
    static bool attr_done = false;
    if (!s1) {
        cudaStreamCreateWithFlags(&s1, cudaStreamNonBlocking);
        cudaEventCreateWithFlags(&evFork, cudaEventDisableTiming);
        cudaEventCreateWithFlags(&evJoin, cudaEventDisableTiming);
    }
    if (!attr_done) {
        cudaFuncSetAttribute(scores_kernel, cudaFuncAttributeMaxDynamicSharedMemorySize, SC_SMEM);
        cudaFuncSetAttribute(av_kernel,     cudaFuncAttributeMaxDynamicSharedMemorySize, AV_SMEM);
        attr_done = true;
    }

    int want_attn = ((size_t)out_size >= (size_t)OUT_ELEMS + ATTN_ELEMS) ? 1 : 0;

    // serial prefix on stream 0
    gemm3_kernel<<<600, 256>>>(xmm, Wq, xv, xa, Wkv);
    scores_kernel<<<AVB, 256, SC_SMEM>>>();

    // fork: side stream runs AV -> proj -> epilogue; stream 0 streams attn
    cudaEventRecord(evFork, 0);
    cudaStreamWaitEvent(s1, evFork, 0);

    if (want_attn) attn_write_kernel<<<NROWS, 256>>>(out + OUT_ELEMS);

    av_kernel<<<AVB, 256, AV_SMEM, s1>>>();
    proj_kernel<<<336, 256, 0, s1>>>(Wproj);
    proj_epilogue_kernel<<<(OUT_ELEMS / 4 + 255) / 256, 256, 0, s1>>>(bproj, out);

    // join
    cudaEventRecord(evJoin, s1);
    cudaStreamWaitEvent(0, evJoin, 0);
}

// round 16
// speedup vs baseline: 1.0285x; 1.0285x over previous
#include <cuda_runtime.h>
#include <math.h>

// ---------------- problem constants ----------------
#define BB   4
#define NMM  196
#define NA   64
#define NV   196
#define DIMI 768
#define NH   12
#define HD   64
#define DIMO 768
#define NKV  (NV*NA)      // 12544
#define SCALE 0.125f      // (768/12)^-0.5

#define OUT_ELEMS  (BB*NMM*DIMO)           // 602112
#define ATTN_ELEMS ((size_t)BB*NH*NMM*NKV) // 118013952
#define NROWS      (BB*NH*NMM)             // 9408 attn rows

typedef unsigned long long ull;

// ---------------- scratch (no allocs allowed) ----------------
// input projections: split-K x2 partials, consumer sums on load
__device__ float g_q0  [BB*NMM*DIMO];
__device__ float g_q1  [BB*NMM*DIMO];
__device__ float g_kvv0[BB*NV*2*DIMO];
__device__ float g_kvv1[BB*NV*2*DIMO];
__device__ float g_kva0[BB*NA*2*DIMO];
__device__ float g_kva1[BB*NA*2*DIMO];
__device__ float g_pv  [BB*NH*NMM*NV];
__device__ float g_pa  [BB*NH*NMM*NA];
__device__ float g_oav [BB*NMM*DIMO];
// output projection: split-K x4 partials
__device__ float g_op0 [OUT_ELEMS];
__device__ float g_op1 [OUT_ELEMS];
__device__ float g_op2 [OUT_ELEMS];
__device__ float g_op3 [OUT_ELEMS];

// ---------------- f32x2 helpers ----------------
__device__ __forceinline__ ull pack2(float x, float y) {
    ull r; asm("mov.b64 %0, {%1,%2};" : "=l"(r) : "f"(x), "f"(y)); return r;
}
__device__ __forceinline__ float2 unpk2(ull v) {
    float2 r; asm("mov.b64 {%0,%1}, %2;" : "=f"(r.x), "=f"(r.y) : "l"(v)); return r;
}
__device__ __forceinline__ ull fma2(ull a, ull b, ull c) {
    ull d; asm("fma.rn.f32x2 %0, %1, %2, %3;" : "=l"(d) : "l"(a), "l"(b), "l"(c)); return d;
}

// ---------------- warp reductions ----------------
__device__ __forceinline__ float warpMax(float v) {
#pragma unroll
    for (int o = 16; o; o >>= 1) v = fmaxf(v, __shfl_xor_sync(0xffffffffu, v, o));
    return v;
}
__device__ __forceinline__ float warpSum(float v) {
#pragma unroll
    for (int o = 16; o; o >>= 1) v += __shfl_xor_sync(0xffffffffu, v, o);
    return v;
}

// sum-of-2-partials loader
__device__ __forceinline__ float2 sum2_f2(const float* p0, const float* p1, size_t off) {
    float2 a = *(const float2*)(p0 + off);
    float2 b = *(const float2*)(p1 + off);
    return make_float2(a.x + b.x, a.y + b.y);
}

// ========== 128x128 FFMA2 GEMM tile, split-K, DOUBLE-BUFFERED slabs ==========
// One __syncthreads per 16-k slab: stores for slab s+1 go to the idle buffer
// while compute reads the current one, so the trailing barrier is unnecessary.
#define GP 132
#define GEMM_SMEM (4 * 16 * GP)   // floats (2 buffers x (As+Bs))

template<int M, int N, int K>
__device__ __forceinline__ void gemm128(const float* __restrict__ A,
                                        const float* __restrict__ B,
                                        float* __restrict__ C,
                                        int mt, int nt, int kbeg, int kend,
                                        float* sm)
{
    const int tid = threadIdx.x;
    const int tx = tid & 15, ty = tid >> 4;
    const int m0 = mt * 128, n0 = nt * 128;

    const int ar = tid >> 1, ak = (tid & 1) * 8;
    const int br = tid >> 4, bc = (tid & 15) * 8;

    ull acc[8][4];
#pragma unroll
    for (int i = 0; i < 8; i++)
#pragma unroll
        for (int j = 0; j < 4; j++) acc[i][j] = 0ULL;

    const bool aval = (m0 + ar < M);
    const float* Aptr = A + (size_t)(m0 + ar) * K + kbeg + ak;
    const float* Bptr = B + (size_t)(kbeg + br) * N + n0 + bc;

    const float4 z4 = make_float4(0.f, 0.f, 0.f, 0.f);
    float4 ra0 = aval ? *(const float4*)(Aptr)     : z4;
    float4 ra1 = aval ? *(const float4*)(Aptr + 4) : z4;
    float4 rb0 = *(const float4*)(Bptr);
    float4 rb1 = *(const float4*)(Bptr + 4);

    int buf = 0;
    for (int k0 = kbeg; k0 < kend; k0 += 16, buf ^= 1) {
        float* As = sm + buf * (32 * GP);            // [16][GP] k-major
        float* Bs = sm + buf * (32 * GP) + 16 * GP;  // [16][GP]

        As[(ak + 0) * GP + ar] = ra0.x;
        As[(ak + 1) * GP + ar] = ra0.y;
        As[(ak + 2) * GP + ar] = ra0.z;
        As[(ak + 3) * GP + ar] = ra0.w;
        As[(ak + 4) * GP + ar] = ra1.x;
        As[(ak + 5) * GP + ar] = ra1.y;
        As[(ak + 6) * GP + ar] = ra1.z;
        As[(ak + 7) * GP + ar] = ra1.w;
        *(float4*)&Bs[br * GP + bc]     = rb0;
        *(float4*)&Bs[br * GP + bc + 4] = rb1;
        __syncthreads();

        if (k0 + 16 < kend) {
            Aptr += 16;
            Bptr += (size_t)16 * N;
            ra0 = aval ? *(const float4*)(Aptr)     : z4;
            ra1 = aval ? *(const float4*)(Aptr + 4) : z4;
            rb0 = *(const float4*)(Bptr);
            rb1 = *(const float4*)(Bptr + 4);
        }

#pragma unroll
        for (int k = 0; k < 16; k++) {
            float4 av0 = *(const float4*)&As[k * GP + ty * 8];
            float4 av1 = *(const float4*)&As[k * GP + ty * 8 + 4];
            ulonglong2 bu0 = *(const ulonglong2*)&Bs[k * GP + tx * 8];
            ulonglong2 bu1 = *(const ulonglong2*)&Bs[k * GP + tx * 8 + 4];
            ull bv0 = bu0.x, bv1 = bu0.y, bv2 = bu1.x, bv3 = bu1.y;
            float a[8] = {av0.x, av0.y, av0.z, av0.w, av1.x, av1.y, av1.z, av1.w};
#pragma unroll
            for (int i = 0; i < 8; i++) {
                ull d = pack2(a[i], a[i]);
                acc[i][0] = fma2(d, bv0, acc[i][0]);
                acc[i][1] = fma2(d, bv1, acc[i][1]);
                acc[i][2] = fma2(d, bv2, acc[i][2]);
                acc[i][3] = fma2(d, bv3, acc[i][3]);
            }
        }
        // no trailing sync: next slab's stores target the other buffer
    }

#pragma unroll
    for (int i = 0; i < 8; i++) {
        int gm = m0 + ty * 8 + i;
        if (gm >= M) continue;
        float2 p0 = unpk2(acc[i][0]), p1 = unpk2(acc[i][1]);
        float2 p2 = unpk2(acc[i][2]), p3 = unpk2(acc[i][3]);
        float* crow = &C[(size_t)gm * N + n0 + tx * 8];
        *(float4*)(crow)     = make_float4(p0.x, p0.y, p1.x, p1.y);
        *(float4*)(crow + 4) = make_float4(p2.x, p2.y, p3.x, p3.y);
    }
}

// input projections, split-K x2 -> 300 blocks
__global__ __launch_bounds__(256, 2)
void gemm3_kernel(const float* __restrict__ xmm, const float* __restrict__ Wq,
                  const float* __restrict__ xv,  const float* __restrict__ xa,
                  const float* __restrict__ Wkv)
{
    __shared__ __align__(16) float sm[GEMM_SMEM];
    int bid = blockIdx.x;
    if (bid < 84) {
        int t = bid >> 1, c = bid & 1;
        gemm128<784, 768, 768>(xmm, Wq, c ? g_q1 : g_q0,
                               t / 6, t % 6, c * 384, c * 384 + 384, sm);
    } else if (bid < 252) {
        int l = bid - 84; int t = l >> 1, c = l & 1;
        gemm128<784, 1536, 768>(xv, Wkv, c ? g_kvv1 : g_kvv0,
                                t / 12, t % 12, c * 384, c * 384 + 384, sm);
    } else {
        int l = bid - 252; int t = l >> 1, c = l & 1;
        gemm128<256, 1536, 768>(xa, Wkv + (size_t)DIMI * 1536, c ? g_kva1 : g_kva0,
                                t / 12, t % 12, c * 384, c * 384 + 384, sm);
    }
}

// output projection split-K x4 -> 168 blocks
__global__ __launch_bounds__(256, 2)
void proj_kernel(const float* __restrict__ Wproj)
{
    __shared__ __align__(16) float sm[GEMM_SMEM];
    int t = blockIdx.x >> 2, c = blockIdx.x & 3;
    float* dst = (c == 0) ? g_op0 : (c == 1) ? g_op1 : (c == 2) ? g_op2 : g_op3;
    gemm128<784, 768, 768>(g_oav, Wproj, dst, t / 6, t % 6, c * 192, c * 192 + 192, sm);
}

// epilogue: out = op0+op1+op2+op3 + bias
__global__ __launch_bounds__(256)
void proj_epilogue_kernel(const float* __restrict__ bproj, float* __restrict__ out)
{
    int i4 = blockIdx.x * 256 + threadIdx.x;
    if (i4 >= OUT_ELEMS / 4) return;
    float4 a = ((const float4*)g_op0)[i4];
    float4 b = ((const float4*)g_op1)[i4];
    float4 c = ((const float4*)g_op2)[i4];
    float4 d = ((const float4*)g_op3)[i4];
    int nb = (i4 * 4) % DIMO;
    float4 r = make_float4(a.x + b.x + c.x + d.x + bproj[nb + 0],
                           a.y + b.y + c.y + d.y + bproj[nb + 1],
                           a.z + b.z + c.z + d.z + bproj[nb + 2],
                           a.w + b.w + c.w + d.w + bproj[nb + 3]);
    ((float4*)out)[i4] = r;
}

// ============ scores + softmax (warp-per-q), K tiles only ============
#define QC 28
#define KPAD 66
#define SC_SMEM  ((NV * KPAD + NA * KPAD + 8 * KPAD) * 4)

__global__ __launch_bounds__(256, 2)
void scores_kernel() {
    extern __shared__ float smem[];
    float* Kv  = smem;                 // 196*66
    float* Ka  = Kv + NV * KPAD;       // 64*66
    float* qsm = Ka + NA * KPAD;       // 8*66

    const int blk = blockIdx.x;
    const int c = blk % 7;
    const int h = (blk / 7) % NH;
    const int b = blk / (7 * NH);
    const int tid = threadIdx.x, lane = tid & 31, w = tid >> 5;

    for (int idx = tid; idx < 260 * 32; idx += 256) {
        int r = idx >> 5, d2 = (idx & 31) * 2;
        if (r < NV) {
            size_t off = (size_t)(b * NV + r) * 1536 + h * HD + d2;
            *(float2*)&Kv[r * KPAD + d2] = sum2_f2(g_kvv0, g_kvv1, off);
        } else {
            int j = r - NV;
            size_t off = (size_t)(b * NA + j) * 1536 + h * HD + d2;
            *(float2*)&Ka[j * KPAD + d2] = sum2_f2(g_kva0, g_kva1, off);
        }
    }
    __syncthreads();

#pragma unroll 1
    for (int t0 = 0; t0 < 4; t0++) {
        int rloc = t0 * 8 + w;
        if (rloc >= QC) break;
        int qq = c * QC + rloc;

        size_t qoff = (size_t)(b * NMM + qq) * DIMO + h * HD + lane * 2;
        *(float2*)&qsm[w * KPAD + lane * 2] = sum2_f2(g_q0, g_q1, qoff);
        __syncwarp();
        ull q2[32];
#pragma unroll
        for (int u = 0; u < 32; u++) q2[u] = *(const ull*)&qsm[w * KPAD + 2 * u];

        float sv[7], sa[2];
#pragma unroll
        for (int t = 0; t < 7; t++) {
            int i = 32 * t + lane;
            float s = -1e30f;
            if (i < NV) {
                const float* kr = &Kv[i * KPAD];
                ull acc = 0ULL;
#pragma unroll
                for (int u = 0; u < 32; u++) acc = fma2(q2[u], *(const ull*)&kr[2 * u], acc);
                float2 p = unpk2(acc);
                s = (p.x + p.y) * SCALE;
            }
            sv[t] = s;
        }
#pragma unroll
        for (int t = 0; t < 2; t++) {
            int j = 32 * t + lane;
            const float* kr = &Ka[j * KPAD];
            ull acc = 0ULL;
#pragma unroll
            for (int u = 0; u < 32; u++) acc = fma2(q2[u], *(const ull*)&kr[2 * u], acc);
            float2 p = unpk2(acc);
            sa[t] = (p.x + p.y) * SCALE;
        }

        float mv = sv[0];
#pragma unroll
        for (int t = 1; t < 7; t++) mv = fmaxf(mv, sv[t]);
        mv = warpMax(mv);
        float ma = fmaxf(sa[0], sa[1]);
        ma = warpMax(ma);

        float ev[7], ea[2], Sv = 0.f, Sa = 0.f;
#pragma unroll
        for (int t = 0; t < 7; t++) { ev[t] = __expf(sv[t] - mv); Sv += ev[t]; }
#pragma unroll
        for (int t = 0; t < 2; t++) { ea[t] = __expf(sa[t] - ma); Sa += ea[t]; }
        float iEv = 1.f / warpSum(Sv);
        float iEa = 1.f / warpSum(Sa);

        size_t rowg = (size_t)(b * NH + h) * NMM + qq;
#pragma unroll
        for (int t = 0; t < 7; t++) {
            int i = 32 * t + lane;
            if (i < NV) g_pv[rowg * NV + i] = ev[t] * iEv;
        }
#pragma unroll
        for (int t = 0; t < 2; t++) g_pa[rowg * NA + 32 * t + lane] = ea[t] * iEa;
    }
}

// ============ AV: 4 rows/warp, smem-staged packed probabilities ============
// Inner loop has NO shuffles: per 32-k chunk, each lane stages (p,p) pairs for
// its 4 rows into a per-warp smem scratch (STS.64), then the hot loop is
// LDS.64(V) + 4x [LDS.64 broadcast(p2) -> fma2] with 4 independent chains.
#define AVB  (BB*NH*7)   // 336
#define AV_SMEM  ((NV * KPAD + NA * KPAD) * 4 + 8 * 4 * 32 * 8)  // V tiles + p-stage

__global__ __launch_bounds__(256, 2)
void av_kernel()
{
    extern __shared__ float smem[];
    float* Vv = smem;              // 196*66
    float* Va = Vv + NV * KPAD;    // 64*66
    ull* pst = (ull*)(Va + NA * KPAD);  // [8 warps][4 rows][32]
    const int bid = blockIdx.x;
    const int c = bid % 7;
    const int h = (bid / 7) % NH;
    const int b = bid / (7 * NH);
    const int tid = threadIdx.x, lane = tid & 31, w = tid >> 5;

    for (int idx = tid; idx < 260 * 32; idx += 256) {
        int r = idx >> 5, d2 = (idx & 31) * 2;
        if (r < NV) {
            size_t off = (size_t)(b * NV + r) * 1536 + 768 + h * HD + d2;
            *(float2*)&Vv[r * KPAD + d2] = sum2_f2(g_kvv0, g_kvv1, off);
        } else {
            int j = r - NV;
            size_t off = (size_t)(b * NA + j) * 1536 + 768 + h * HD + d2;
            *(float2*)&Va[j * KPAD + d2] = sum2_f2(g_kva0, g_kva1, off);
        }
    }
    __syncthreads();

    // gather probabilities for this warp's 4 rows (rloc = r*8 + w)
    bool valid[4];
    float ev[4][7], ea[4][2];
    int qqr[4];
#pragma unroll
    for (int r = 0; r < 4; r++) {
        int rloc = r * 8 + w;
        valid[r] = (rloc < QC);
        int qq = c * QC + (valid[r] ? rloc : 0);
        qqr[r] = qq;
        size_t rowg = (size_t)(b * NH + h) * NMM + qq;
#pragma unroll
        for (int t = 0; t < 7; t++) {
            int i = 32 * t + lane;
            ev[r][t] = (valid[r] && i < NV) ? g_pv[rowg * NV + i] : 0.f;
        }
#pragma unroll
        for (int t = 0; t < 2; t++)
            ea[r][t] = valid[r] ? g_pa[rowg * NA + 32 * t + lane] : 0.f;
    }

    ull* myst = pst + w * 128;   // this warp's [4][32] stage
    ull acc[4] = {0ULL, 0ULL, 0ULL, 0ULL};

#pragma unroll
    for (int t = 0; t < 7; t++) {
        // stage packed (p,p) for 4 rows
#pragma unroll
        for (int r = 0; r < 4; r++)
            myst[r * 32 + lane] = pack2(ev[r][t], ev[r][t]);
        __syncwarp();
        int smax = (t == 6) ? 4 : 32;
#pragma unroll 4
        for (int s = 0; s < 32; s++) {
            if (s >= smax) break;
            ull vv = *(const ull*)&Vv[(32 * t + s) * KPAD + 2 * lane];
            acc[0] = fma2(myst[s],      vv, acc[0]);
            acc[1] = fma2(myst[32 + s], vv, acc[1]);
            acc[2] = fma2(myst[64 + s], vv, acc[2]);
            acc[3] = fma2(myst[96 + s], vv, acc[3]);
        }
        __syncwarp();
    }
#pragma unroll
    for (int t = 0; t < 2; t++) {
#pragma unroll
        for (int r = 0; r < 4; r++)
            myst[r * 32 + lane] = pack2(ea[r][t], ea[r][t]);
        __syncwarp();
#pragma unroll 4
        for (int s = 0; s < 32; s++) {
            ull vv = *(const ull*)&Va[(32 * t + s) * KPAD + 2 * lane];
            acc[0] = fma2(myst[s],      vv, acc[0]);
            acc[1] = fma2(myst[32 + s], vv, acc[1]);
            acc[2] = fma2(myst[64 + s], vv, acc[2]);
            acc[3] = fma2(myst[96 + s], vv, acc[3]);
        }
        __syncwarp();
    }

#pragma unroll
    for (int r = 0; r < 4; r++) {
        if (!valid[r]) continue;
        float2 o = unpk2(acc[r]);
        *(float2*)&g_oav[(size_t)(b * NMM + qqr[r]) * DIMO + h * HD + 2 * lane] = o;
    }
}

// ---------- attn materialization: lightweight 32-reg writer (R5-proven) ----------
__global__ void attn_write_kernel(float* __restrict__ attn_out) {
    __shared__ float pvs[NV];
    __shared__ __align__(16) float4 pas4[NA / 4];
    size_t row = blockIdx.x;
    int tid = threadIdx.x;

    for (int i = tid; i < NV; i += 256) pvs[i] = g_pv[row * NV + i];
    if (tid < NA / 4) pas4[tid] = ((const float4*)(g_pa + row * NA))[tid];
    __syncthreads();

    float4* out4 = (float4*)(attn_out + row * (size_t)NKV);
#pragma unroll 4
    for (int k4 = tid; k4 < NKV / 4; k4 += 256) {
        int i  = k4 >> 4;
        int j4 = k4 & 15;
        float p = pvs[i];
        float4 a = pas4[j4];
        float4 v = make_float4(p * a.x, p * a.y, p * a.z, p * a.w);
        __stcs(&out4[k4], v);
    }
}

// ---------------- host launcher ----------------
extern "C" void kernel_launch(void* const* d_in, const int* in_sizes, int n_in,
                              void* d_out, int out_size)
{
    const float* xmm   = (const float*)d_in[0];
    const float* xa    = (const float*)d_in[1];
    const float* xv    = (const float*)d_in[2];
    const float* Wq    = (const float*)d_in[3];
    const float* Wkv   = (const float*)d_in[4];
    const float* Wproj = (const float*)d_in[5];
    const float* bproj = (const float*)d_in[6];
    float* out = (float*)d_out;

    static bool attr_done = false;
    if (!attr_done) {
        cudaFuncSetAttribute(scores_kernel, cudaFuncAttributeMaxDynamicSharedMemorySize, SC_SMEM);
        cudaFuncSetAttribute(av_kernel,     cudaFuncAttributeMaxDynamicSharedMemorySize, AV_SMEM);
        attr_done = true;
    }

    int want_attn = ((size_t)out_size >= (size_t)OUT_ELEMS + ATTN_ELEMS) ? 1 : 0;

    gemm3_kernel<<<300, 256>>>(xmm, Wq, xv, xa, Wkv);
    scores_kernel<<<AVB, 256, SC_SMEM>>>();
    av_kernel<<<AVB, 256, AV_SMEM>>>();
    if (want_attn) attn_write_kernel<<<NROWS, 256>>>(out + OUT_ELEMS);
    proj_kernel<<<168, 256>>>(Wproj);
    proj_epilogue_kernel<<<(OUT_ELEMS / 4 + 255) / 256, 256>>>(bproj, out);
}

// round 17
// speedup vs baseline: 1.0927x; 1.0624x over previous
#include <cuda_runtime.h>
#include <math.h>

// ---------------- problem constants ----------------
#define BB   4
#define NMM  196
#define NA   64
#define NV   196
#define DIMI 768
#define NH   12
#define HD   64
#define DIMO 768
#define NKV  (NV*NA)      // 12544
#define SCALE 0.125f      // (768/12)^-0.5

#define OUT_ELEMS  (BB*NMM*DIMO)           // 602112
#define ATTN_ELEMS ((size_t)BB*NH*NMM*NKV) // 118013952
#define NROWS      (BB*NH*NMM)             // 9408 attn rows

typedef unsigned long long ull;

// ---------------- scratch (no allocs allowed) ----------------
// input projections: split-K x2 partials, consumer sums on load
__device__ float g_q0  [BB*NMM*DIMO];
__device__ float g_q1  [BB*NMM*DIMO];
__device__ float g_kvv0[BB*NV*2*DIMO];
__device__ float g_kvv1[BB*NV*2*DIMO];
__device__ float g_kva0[BB*NA*2*DIMO];
__device__ float g_kva1[BB*NA*2*DIMO];
__device__ float g_pv  [BB*NH*NMM*NV];
__device__ float g_pa  [BB*NH*NMM*NA];
__device__ float g_oav [BB*NMM*DIMO];
// output projection: split-K x4 partials
__device__ float g_op0 [OUT_ELEMS];
__device__ float g_op1 [OUT_ELEMS];
__device__ float g_op2 [OUT_ELEMS];
__device__ float g_op3 [OUT_ELEMS];

// ---------------- f32x2 helpers ----------------
__device__ __forceinline__ ull pack2(float x, float y) {
    ull r; asm("mov.b64 %0, {%1,%2};" : "=l"(r) : "f"(x), "f"(y)); return r;
}
__device__ __forceinline__ float2 unpk2(ull v) {
    float2 r; asm("mov.b64 {%0,%1}, %2;" : "=f"(r.x), "=f"(r.y) : "l"(v)); return r;
}
__device__ __forceinline__ ull fma2(ull a, ull b, ull c) {
    ull d; asm("fma.rn.f32x2 %0, %1, %2, %3;" : "=l"(d) : "l"(a), "l"(b), "l"(c)); return d;
}

// ---------------- warp reductions ----------------
__device__ __forceinline__ float warpMax(float v) {
#pragma unroll
    for (int o = 16; o; o >>= 1) v = fmaxf(v, __shfl_xor_sync(0xffffffffu, v, o));
    return v;
}
__device__ __forceinline__ float warpSum(float v) {
#pragma unroll
    for (int o = 16; o; o >>= 1) v += __shfl_xor_sync(0xffffffffu, v, o);
    return v;
}

// sum-of-2-partials loader
__device__ __forceinline__ float2 sum2_f2(const float* p0, const float* p1, size_t off) {
    float2 a = *(const float2*)(p0 + off);
    float2 b = *(const float2*)(p1 + off);
    return make_float2(a.x + b.x, a.y + b.y);
}

// ========== 128x128 FFMA2 GEMM tile, split-K, double-buffered slabs ==========
#define GP 132
#define GEMM_SMEM (4 * 16 * GP)   // floats (2 buffers x (As+Bs))

template<int M, int N, int K>
__device__ __forceinline__ void gemm128(const float* __restrict__ A,
                                        const float* __restrict__ B,
                                        float* __restrict__ C,
                                        int mt, int nt, int kbeg, int kend,
                                        float* sm)
{
    const int tid = threadIdx.x;
    const int tx = tid & 15, ty = tid >> 4;
    const int m0 = mt * 128, n0 = nt * 128;

    const int ar = tid >> 1, ak = (tid & 1) * 8;
    const int br = tid >> 4, bc = (tid & 15) * 8;

    ull acc[8][4];
#pragma unroll
    for (int i = 0; i < 8; i++)
#pragma unroll
        for (int j = 0; j < 4; j++) acc[i][j] = 0ULL;

    const bool aval = (m0 + ar < M);
    const float* Aptr = A + (size_t)(m0 + ar) * K + kbeg + ak;
    const float* Bptr = B + (size_t)(kbeg + br) * N + n0 + bc;

    const float4 z4 = make_float4(0.f, 0.f, 0.f, 0.f);
    float4 ra0 = aval ? *(const float4*)(Aptr)     : z4;
    float4 ra1 = aval ? *(const float4*)(Aptr + 4) : z4;
    float4 rb0 = *(const float4*)(Bptr);
    float4 rb1 = *(const float4*)(Bptr + 4);

    int buf = 0;
    for (int k0 = kbeg; k0 < kend; k0 += 16, buf ^= 1) {
        float* As = sm + buf * (32 * GP);
        float* Bs = sm + buf * (32 * GP) + 16 * GP;

        As[(ak + 0) * GP + ar] = ra0.x;
        As[(ak + 1) * GP + ar] = ra0.y;
        As[(ak + 2) * GP + ar] = ra0.z;
        As[(ak + 3) * GP + ar] = ra0.w;
        As[(ak + 4) * GP + ar] = ra1.x;
        As[(ak + 5) * GP + ar] = ra1.y;
        As[(ak + 6) * GP + ar] = ra1.z;
        As[(ak + 7) * GP + ar] = ra1.w;
        *(float4*)&Bs[br * GP + bc]     = rb0;
        *(float4*)&Bs[br * GP + bc + 4] = rb1;
        __syncthreads();

        if (k0 + 16 < kend) {
            Aptr += 16;
            Bptr += (size_t)16 * N;
            ra0 = aval ? *(const float4*)(Aptr)     : z4;
            ra1 = aval ? *(const float4*)(Aptr + 4) : z4;
            rb0 = *(const float4*)(Bptr);
            rb1 = *(const float4*)(Bptr + 4);
        }

#pragma unroll
        for (int k = 0; k < 16; k++) {
            float4 av0 = *(const float4*)&As[k * GP + ty * 8];
            float4 av1 = *(const float4*)&As[k * GP + ty * 8 + 4];
            ulonglong2 bu0 = *(const ulonglong2*)&Bs[k * GP + tx * 8];
            ulonglong2 bu1 = *(const ulonglong2*)&Bs[k * GP + tx * 8 + 4];
            ull bv0 = bu0.x, bv1 = bu0.y, bv2 = bu1.x, bv3 = bu1.y;
            float a[8] = {av0.x, av0.y, av0.z, av0.w, av1.x, av1.y, av1.z, av1.w};
#pragma unroll
            for (int i = 0; i < 8; i++) {
                ull d = pack2(a[i], a[i]);
                acc[i][0] = fma2(d, bv0, acc[i][0]);
                acc[i][1] = fma2(d, bv1, acc[i][1]);
                acc[i][2] = fma2(d, bv2, acc[i][2]);
                acc[i][3] = fma2(d, bv3, acc[i][3]);
            }
        }
        // no trailing sync: next slab's stores target the other buffer
    }

#pragma unroll
    for (int i = 0; i < 8; i++) {
        int gm = m0 + ty * 8 + i;
        if (gm >= M) continue;
        float2 p0 = unpk2(acc[i][0]), p1 = unpk2(acc[i][1]);
        float2 p2 = unpk2(acc[i][2]), p3 = unpk2(acc[i][3]);
        float* crow = &C[(size_t)gm * N + n0 + tx * 8];
        *(float4*)(crow)     = make_float4(p0.x, p0.y, p1.x, p1.y);
        *(float4*)(crow + 4) = make_float4(p2.x, p2.y, p3.x, p3.y);
    }
}

// input projections, split-K x2 -> 300 blocks
__global__ __launch_bounds__(256, 2)
void gemm3_kernel(const float* __restrict__ xmm, const float* __restrict__ Wq,
                  const float* __restrict__ xv,  const float* __restrict__ xa,
                  const float* __restrict__ Wkv)
{
    __shared__ __align__(16) float sm[GEMM_SMEM];
    int bid = blockIdx.x;
    if (bid < 84) {
        int t = bid >> 1, c = bid & 1;
        gemm128<784, 768, 768>(xmm, Wq, c ? g_q1 : g_q0,
                               t / 6, t % 6, c * 384, c * 384 + 384, sm);
    } else if (bid < 252) {
        int l = bid - 84; int t = l >> 1, c = l & 1;
        gemm128<784, 1536, 768>(xv, Wkv, c ? g_kvv1 : g_kvv0,
                                t / 12, t % 12, c * 384, c * 384 + 384, sm);
    } else {
        int l = bid - 252; int t = l >> 1, c = l & 1;
        gemm128<256, 1536, 768>(xa, Wkv + (size_t)DIMI * 1536, c ? g_kva1 : g_kva0,
                                t / 12, t % 12, c * 384, c * 384 + 384, sm);
    }
}

// output projection split-K x4 -> 168 blocks
__global__ __launch_bounds__(256, 2)
void proj_kernel(const float* __restrict__ Wproj)
{
    __shared__ __align__(16) float sm[GEMM_SMEM];
    int t = blockIdx.x >> 2, c = blockIdx.x & 3;
    float* dst = (c == 0) ? g_op0 : (c == 1) ? g_op1 : (c == 2) ? g_op2 : g_op3;
    gemm128<784, 768, 768>(g_oav, Wproj, dst, t / 6, t % 6, c * 192, c * 192 + 192, sm);
}

// epilogue: out = op0+op1+op2+op3 + bias
__global__ __launch_bounds__(256)
void proj_epilogue_kernel(const float* __restrict__ bproj, float* __restrict__ out)
{
    int i4 = blockIdx.x * 256 + threadIdx.x;
    if (i4 >= OUT_ELEMS / 4) return;
    float4 a = ((const float4*)g_op0)[i4];
    float4 b = ((const float4*)g_op1)[i4];
    float4 c = ((const float4*)g_op2)[i4];
    float4 d = ((const float4*)g_op3)[i4];
    int nb = (i4 * 4) % DIMO;
    float4 r = make_float4(a.x + b.x + c.x + d.x + bproj[nb + 0],
                           a.y + b.y + c.y + d.y + bproj[nb + 1],
                           a.z + b.z + c.z + d.z + bproj[nb + 2],
                           a.w + b.w + c.w + d.w + bproj[nb + 3]);
    ((float4*)out)[i4] = r;
}

// ============ scores + softmax (warp-per-q), K tiles only ============
#define QC 28
#define KPAD 66
#define SC_SMEM  ((NV * KPAD + NA * KPAD + 8 * KPAD) * 4)

__global__ __launch_bounds__(256, 2)
void scores_kernel() {
    extern __shared__ float smem[];
    float* Kv  = smem;                 // 196*66
    float* Ka  = Kv + NV * KPAD;       // 64*66
    float* qsm = Ka + NA * KPAD;       // 8*66

    const int blk = blockIdx.x;
    const int c = blk % 7;
    const int h = (blk / 7) % NH;
    const int b = blk / (7 * NH);
    const int tid = threadIdx.x, lane = tid & 31, w = tid >> 5;

    for (int idx = tid; idx < 260 * 32; idx += 256) {
        int r = idx >> 5, d2 = (idx & 31) * 2;
        if (r < NV) {
            size_t off = (size_t)(b * NV + r) * 1536 + h * HD + d2;
            *(float2*)&Kv[r * KPAD + d2] = sum2_f2(g_kvv0, g_kvv1, off);
        } else {
            int j = r - NV;
            size_t off = (size_t)(b * NA + j) * 1536 + h * HD + d2;
            *(float2*)&Ka[j * KPAD + d2] = sum2_f2(g_kva0, g_kva1, off);
        }
    }
    __syncthreads();

#pragma unroll 1
    for (int t0 = 0; t0 < 4; t0++) {
        int rloc = t0 * 8 + w;
        if (rloc >= QC) break;
        int qq = c * QC + rloc;

        size_t qoff = (size_t)(b * NMM + qq) * DIMO + h * HD + lane * 2;
        *(float2*)&qsm[w * KPAD + lane * 2] = sum2_f2(g_q0, g_q1, qoff);
        __syncwarp();
        ull q2[32];
#pragma unroll
        for (int u = 0; u < 32; u++) q2[u] = *(const ull*)&qsm[w * KPAD + 2 * u];

        float sv[7], sa[2];
#pragma unroll
        for (int t = 0; t < 7; t++) {
            int i = 32 * t + lane;
            float s = -1e30f;
            if (i < NV) {
                const float* kr = &Kv[i * KPAD];
                ull acc = 0ULL;
#pragma unroll
                for (int u = 0; u < 32; u++) acc = fma2(q2[u], *(const ull*)&kr[2 * u], acc);
                float2 p = unpk2(acc);
                s = (p.x + p.y) * SCALE;
            }
            sv[t] = s;
        }
#pragma unroll
        for (int t = 0; t < 2; t++) {
            int j = 32 * t + lane;
            const float* kr = &Ka[j * KPAD];
            ull acc = 0ULL;
#pragma unroll
            for (int u = 0; u < 32; u++) acc = fma2(q2[u], *(const ull*)&kr[2 * u], acc);
            float2 p = unpk2(acc);
            sa[t] = (p.x + p.y) * SCALE;
        }

        float mv = sv[0];
#pragma unroll
        for (int t = 1; t < 7; t++) mv = fmaxf(mv, sv[t]);
        mv = warpMax(mv);
        float ma = fmaxf(sa[0], sa[1]);
        ma = warpMax(ma);

        float ev[7], ea[2], Sv = 0.f, Sa = 0.f;
#pragma unroll
        for (int t = 0; t < 7; t++) { ev[t] = __expf(sv[t] - mv); Sv += ev[t]; }
#pragma unroll
        for (int t = 0; t < 2; t++) { ea[t] = __expf(sa[t] - ma); Sa += ea[t]; }
        float iEv = 1.f / warpSum(Sv);
        float iEa = 1.f / warpSum(Sa);

        size_t rowg = (size_t)(b * NH + h) * NMM + qq;
#pragma unroll
        for (int t = 0; t < 7; t++) {
            int i = 32 * t + lane;
            if (i < NV) g_pv[rowg * NV + i] = ev[t] * iEv;
        }
#pragma unroll
        for (int t = 0; t < 2; t++) g_pa[rowg * NA + 32 * t + lane] = ea[t] * iEa;
    }
}

// ======== fused AV (4 rows/warp parallel) + attn write, one launch ========
// blocks 0..335: AV (fma/smem-bound, moderate regs). blocks 336+: write
// blocks (DRAM-bound), 8 rows each. AV hides inside the DRAM write stream.
// Dynamic smem stays 68.6KB -> 3 CTAs/SM for both paths (R9 lesson: no
// 128-reg GEMM in here).
#define AVB   (BB*NH*7)   // 336
#define WROWS 8
#define AVW_SMEM  ((NV * KPAD + NA * KPAD) * 4)

__global__ __launch_bounds__(256, 3)
void av_write_kernel(float* __restrict__ out, int want_attn)
{
    extern __shared__ float smem[];
    int bid = blockIdx.x;
    const int tid = threadIdx.x;

    if (bid < AVB) {
        float* Vv = smem;              // 196*66
        float* Va = Vv + NV * KPAD;    // 64*66
        const int c = bid % 7;
        const int h = (bid / 7) % NH;
        const int b = bid / (7 * NH);
        const int lane = tid & 31, w = tid >> 5;

        for (int idx = tid; idx < 260 * 32; idx += 256) {
            int r = idx >> 5, d2 = (idx & 31) * 2;
            if (r < NV) {
                size_t off = (size_t)(b * NV + r) * 1536 + 768 + h * HD + d2;
                *(float2*)&Vv[r * KPAD + d2] = sum2_f2(g_kvv0, g_kvv1, off);
            } else {
                int j = r - NV;
                size_t off = (size_t)(b * NA + j) * 1536 + 768 + h * HD + d2;
                *(float2*)&Va[j * KPAD + d2] = sum2_f2(g_kva0, g_kva1, off);
            }
        }
        __syncthreads();

        // 4 rows per warp: rloc = r*8 + w
        bool valid[4];
        float ev[4][7], ea[4][2];
        int qqr[4];
#pragma unroll
        for (int r = 0; r < 4; r++) {
            int rloc = r * 8 + w;
            valid[r] = (rloc < QC);
            int qq = c * QC + (valid[r] ? rloc : 0);
            qqr[r] = qq;
            size_t rowg = (size_t)(b * NH + h) * NMM + qq;
#pragma unroll
            for (int t = 0; t < 7; t++) {
                int i = 32 * t + lane;
                ev[r][t] = (valid[r] && i < NV) ? g_pv[rowg * NV + i] : 0.f;
            }
#pragma unroll
            for (int t = 0; t < 2; t++)
                ea[r][t] = valid[r] ? g_pa[rowg * NA + 32 * t + lane] : 0.f;
        }

        ull acc[4] = {0ULL, 0ULL, 0ULL, 0ULL};

#pragma unroll
        for (int t = 0; t < 7; t++) {
            int smax = (t == 6) ? 4 : 32;
#pragma unroll
            for (int s = 0; s < 32; s++) {
                if (s >= smax) break;
                ull vv = *(const ull*)&Vv[(32 * t + s) * KPAD + 2 * lane];
#pragma unroll
                for (int r = 0; r < 4; r++) {
                    float p = __shfl_sync(0xffffffffu, ev[r][t], s);
                    acc[r] = fma2(pack2(p, p), vv, acc[r]);
                }
            }
        }
#pragma unroll
        for (int t = 0; t < 2; t++) {
#pragma unroll
            for (int s = 0; s < 32; s++) {
                ull vv = *(const ull*)&Va[(32 * t + s) * KPAD + 2 * lane];
#pragma unroll
                for (int r = 0; r < 4; r++) {
                    float p = __shfl_sync(0xffffffffu, ea[r][t], s);
                    acc[r] = fma2(pack2(p, p), vv, acc[r]);
                }
            }
        }

#pragma unroll
        for (int r = 0; r < 4; r++) {
            if (!valid[r]) continue;
            float2 o = unpk2(acc[r]);
            *(float2*)&g_oav[(size_t)(b * NMM + qqr[r]) * DIMO + h * HD + 2 * lane] = o;
        }
        return;
    }

    if (!want_attn) return;

    // write path: 8 attn rows per block, streaming float4 stores
    float* pvs = smem;                  // [WROWS][196]
    float* pas = smem + WROWS * NV;     // [WROWS][64]
    size_t row0 = (size_t)(bid - AVB) * WROWS;
    float* attn_out = out + OUT_ELEMS;

    for (int idx = tid; idx < WROWS * NV; idx += 256)
        pvs[idx] = g_pv[row0 * NV + idx];
    for (int idx = tid; idx < WROWS * NA; idx += 256)
        pas[idx] = g_pa[row0 * NA + idx];
    __syncthreads();

#pragma unroll 1
    for (int r = 0; r < WROWS; r++) {
        const float*  pv = pvs + r * NV;
        const float4* pa4 = (const float4*)(pas + r * NA);
        float4* out4 = (float4*)(attn_out + (row0 + r) * (size_t)NKV);
#pragma unroll 4
        for (int k4 = tid; k4 < NKV / 4; k4 += 256) {
            int i  = k4 >> 4;
            int j4 = k4 & 15;
            float p = pv[i];
            float4 a = pa4[j4];
            float4 v = make_float4(p * a.x, p * a.y, p * a.z, p * a.w);
            __stcs(&out4[k4], v);
        }
    }
}

// ---------------- host launcher ----------------
extern "C" void kernel_launch(void* const* d_in, const int* in_sizes, int n_in,
                              void* d_out, int out_size)
{
    const float* xmm   = (const float*)d_in[0];
    const float* xa    = (const float*)d_in[1];
    const float* xv    = (const float*)d_in[2];
    const float* Wq    = (const float*)d_in[3];
    const float* Wkv   = (const float*)d_in[4];
    const float* Wproj = (const float*)d_in[5];
    const float* bproj = (const float*)d_in[6];
    float* out = (float*)d_out;

    static bool attr_done = false;
    if (!attr_done) {
        cudaFuncSetAttribute(scores_kernel,   cudaFuncAttributeMaxDynamicSharedMemorySize, SC_SMEM);
        cudaFuncSetAttribute(av_write_kernel, cudaFuncAttributeMaxDynamicSharedMemorySize, AVW_SMEM);
        attr_done = true;
    }

    int want_attn = ((size_t)out_size >= (size_t)OUT_ELEMS + ATTN_ELEMS) ? 1 : 0;

    gemm3_kernel<<<300, 256>>>(xmm, Wq, xv, xa, Wkv);
    scores_kernel<<<AVB, 256, SC_SMEM>>>();
    int nblk = AVB + (want_attn ? NROWS / WROWS : 0);   // 1512 or 336
    av_write_kernel<<<nblk, 256, AVW_SMEM>>>(out, want_attn);
    proj_kernel<<<168, 256>>>(Wproj);
    proj_epilogue_kernel<<<(OUT_ELEMS / 4 + 255) / 256, 256>>>(bproj, out);
}